// round 15
// baseline (speedup 1.0000x reference)
#include <cuda_runtime.h>
#include <cstdint>
#include <cstddef>

// HugeNet: 10000 x (Linear(100,100)+ReLU) scan, then Linear(100,10).
//
// Round 15: R14 (cluster-2 column split, 64 clusters x 2 CTAs, each SM
// streams only 20.8KB of W/layer) with the memory-ordering bug FIXED:
// the per-layer h-exchange arrive is now release at CLUSTER scope
// (mbarrier.arrive.release.cluster.shared::cluster) so the preceding
// st.shared::cluster data stores are visible to the peer's
// try_wait.parity.acquire.cluster. R14 used the PTX default (.release
// .cta), which let the peer see the count flip before the data.

#define N_LAYERS 10000
#define D        100
#define D_OUT    10
#define THREADS  256
#define QS       7
#define CSTRIDE  (QS * THREADS)          // float4 per (layer, cta) = 1792

typedef unsigned long long ull;

// [(N_LAYERS+2)][2][7][256] float4 (~574MB, zero-padded)
__device__ __align__(16) float4 g_Wp[(size_t)(N_LAYERS + 2) * 2 * CSTRIDE];

__host__ __device__ __forceinline__ int kqb(int kq) {
    return kq ? (28 + 24 * (kq - 1)) : 0;   // {0,28,52,76}
}
__host__ __device__ __forceinline__ int kqn(int kq) {
    return kq ? 6 : 7;
}

// ---------------------------------------------------------------------------
// prep: W[l][j][k] -> g_Wp[((l*2+rho)*QS + q)*256 + t]
//   t: kq=t>>6, jl=t&63;  j = base(rho)+jl;  k = kqb(kq)+4q
// ---------------------------------------------------------------------------
__global__ void prep_kernel(const float* __restrict__ W) {
    size_t idx = (size_t)blockIdx.x * blockDim.x + threadIdx.x;
    const size_t total = (size_t)(N_LAYERS + 2) * 2 * CSTRIDE;
    if (idx >= total) return;
    int    t     = (int)(idx & 255);
    size_t rest  = idx >> 8;
    int    q     = (int)(rest % QS);
    size_t rest2 = rest / QS;
    int    rho   = (int)(rest2 & 1);
    size_t l     = rest2 >> 1;
    int jl = t & 63, kq = t >> 6;
    int cols = rho ? 48 : 52, base = rho ? 52 : 0;
    int j = base + jl, k = kqb(kq) + 4 * q;
    float4 v = make_float4(0.f, 0.f, 0.f, 0.f);
    if (l < N_LAYERS && jl < cols && q < kqn(kq))
        v = *reinterpret_cast<const float4*>(
                W + l * (size_t)(D * D) + (size_t)j * D + k);
    g_Wp[idx] = v;
}

// ---------------------------------------------------------------------------
__device__ __forceinline__ void fma2(ull& a, ull x, ull y) {
    asm("fma.rn.f32x2 %0, %1, %2, %0;" : "+l"(a) : "l"(x), "l"(y));
}
__device__ __forceinline__ float2 upk(ull v) {
    float2 r;
    asm("mov.b64 {%0, %1}, %2;" : "=f"(r.x), "=f"(r.y) : "l"(v));
    return r;
}
__device__ __forceinline__ uint32_t su32(const void* p) {
    return (uint32_t)__cvta_generic_to_shared(p);
}
__device__ __forceinline__ uint32_t mapa32(uint32_t a, uint32_t rk) {
    uint32_t r;
    asm("mapa.shared::cluster.u32 %0, %1, %2;" : "=r"(r) : "r"(a), "r"(rk));
    return r;
}
__device__ __forceinline__ void st_peer(uint32_t a, float v) {
    asm volatile("st.shared::cluster.f32 [%0], %1;" :: "r"(a), "f"(v) : "memory");
}
// FIX: release at CLUSTER scope (R14 used default .release.cta -> the
// st.shared::cluster data was not ordered with the arrival for the peer).
__device__ __forceinline__ void arrive_peer(uint32_t mb) {
    asm volatile("mbarrier.arrive.release.cluster.shared::cluster.b64 _, [%0];"
                 :: "r"(mb) : "memory");
}
__device__ __forceinline__ void waitp(uint32_t mb, unsigned par) {
    unsigned done = 0;
    do {
        asm volatile(
            "{\n\t.reg .pred p;\n\t"
            "mbarrier.try_wait.parity.acquire.cluster.shared::cta.b64 p, [%1], %2, 0x989680;\n\t"
            "selp.b32 %0, 1, 0, p;\n\t}"
            : "=r"(done) : "r"(mb), "r"(par) : "memory");
    } while (!done);
}

__global__ void __launch_bounds__(THREADS, 1) __cluster_dims__(2, 1, 1)
hugenet_kernel(const float* __restrict__ x,
               const float* __restrict__ bg,
               const float* __restrict__ Wo,
               const float* __restrict__ bo,
               float* __restrict__ out) {
    __shared__ __align__(16) float h[2][4][104];   // full h, both halves
    __shared__ __align__(16) float red[4][56][4];  // [kq][jl][row]
    __shared__ __align__(8)  ull   mbar[2];        // one per h buffer

    const int tid = threadIdx.x;
    uint32_t rank;
    asm("mov.u32 %0, %%cluster_ctarank;" : "=r"(rank));
    const uint32_t peer = rank ^ 1;
    const int cols = rank ? 48 : 52;
    const int base = rank ? 52 : 0;
    const int kq = tid >> 6, jl = tid & 63;
    const int kb = kqb(kq);
    const bool liveW = (jl < cols);
    const bool waiter = rank ? (kq < 2) : (kq >= 2);  // k-groups in peer half
    const bool p2 = (tid < cols);
    const int r0 = (int)(blockIdx.x >> 1) * 4;

    const uint32_t mb0 = su32(&mbar[0]);
    const uint32_t hb0 = su32(&h[0][0][0]);
    if (tid == 0) {
        unsigned cnt = (unsigned)(100 - cols);     // peer's writer count
        asm volatile("mbarrier.init.shared.b64 [%0], %1;" :: "r"(mb0), "r"(cnt) : "memory");
        asm volatile("mbarrier.init.shared.b64 [%0], %1;" :: "r"(mb0 + 8), "r"(cnt) : "memory");
    }
    for (int idx = tid; idx < 4 * D; idx += THREADS)
        h[0][idx / D][idx % D] = x[(size_t)(r0 + idx / D) * D + idx % D];
    __syncthreads();
    asm volatile("barrier.cluster.arrive.aligned;" ::: "memory");
    asm volatile("barrier.cluster.wait.aligned;"   ::: "memory");

    const uint32_t hb_r = mapa32(hb0, peer);
    const uint32_t mb_r = mapa32(mb0, peer);

    float4 Wa[QS], Wb[QS];
    float  bA = 0.f, bB = 0.f;

    auto ldW = [&](float4* R, size_t l) {
        if (!liveW) return;
        const float4* p = g_Wp + (l * 2 + rank) * CSTRIDE + tid;
        #pragma unroll
        for (int i = 0; i < 6; i++) R[i] = __ldg(p + i * THREADS);
        if (kq == 0) R[6] = __ldg(p + 6 * THREADS);
    };
    auto ldB = [&](float& b, int l) {
        if (p2 && l < N_LAYERS) b = __ldg(bg + (size_t)l * D + base + tid);
    };

    auto quad = [&](const float4& Rq, const float* hk, int q,
                    ull& a0, ull& a1, ull& a2, ull& a3) {
        ulonglong2 w  = *reinterpret_cast<const ulonglong2*>(&Rq);
        ulonglong2 v0 = *reinterpret_cast<const ulonglong2*>(hk + 4 * q);
        ulonglong2 v1 = *reinterpret_cast<const ulonglong2*>(hk + 104 + 4 * q);
        ulonglong2 v2 = *reinterpret_cast<const ulonglong2*>(hk + 208 + 4 * q);
        ulonglong2 v3 = *reinterpret_cast<const ulonglong2*>(hk + 312 + 4 * q);
        fma2(a0, v0.x, w.x); fma2(a0, v0.y, w.y);
        fma2(a1, v1.x, w.x); fma2(a1, v1.y, w.y);
        fma2(a2, v2.x, w.x); fma2(a2, v2.y, w.y);
        fma2(a3, v3.x, w.x); fma2(a3, v3.y, w.y);
    };

    auto do_layer = [&](const float4* R, float bias, int HB) {
        // ---- phase 1: partials for col base+jl over this k-group ----
        if (liveW) {
            ull a0 = 0ull, a1 = 0ull, a2 = 0ull, a3 = 0ull;
            const float* hk = &h[HB][0][0] + kb;
            #pragma unroll
            for (int q = 0; q < 6; q++) quad(R[q], hk, q, a0, a1, a2, a3);
            if (kq == 0)                quad(R[6], hk, 6, a0, a1, a2, a3);
            float2 u0 = upk(a0), u1 = upk(a1), u2 = upk(a2), u3 = upk(a3);
            *reinterpret_cast<float4*>(&red[kq][jl][0]) =
                make_float4(u0.x + u0.y, u1.x + u1.y, u2.x + u2.y, u3.x + u3.y);
        }
        __syncthreads();

        // ---- phase 2: col base+tid, all 4 rows; write local + peer ----
        if (p2) {
            float4 s0 = *reinterpret_cast<const float4*>(&red[0][tid][0]);
            float4 s1 = *reinterpret_cast<const float4*>(&red[1][tid][0]);
            float4 s2 = *reinterpret_cast<const float4*>(&red[2][tid][0]);
            float4 s3 = *reinterpret_cast<const float4*>(&red[3][tid][0]);
            float v0 = fmaxf(((s0.x + s1.x) + (s2.x + s3.x)) + bias, 0.f);
            float v1 = fmaxf(((s0.y + s1.y) + (s2.y + s3.y)) + bias, 0.f);
            float v2 = fmaxf(((s0.z + s1.z) + (s2.z + s3.z)) + bias, 0.f);
            float v3 = fmaxf(((s0.w + s1.w) + (s2.w + s3.w)) + bias, 0.f);
            const int c = base + tid;
            h[HB ^ 1][0][c] = v0;
            h[HB ^ 1][1][c] = v1;
            h[HB ^ 1][2][c] = v2;
            h[HB ^ 1][3][c] = v3;
            uint32_t ra = hb_r + (uint32_t)((HB ^ 1) * 1664 + c * 4);
            st_peer(ra,        v0);
            st_peer(ra + 416,  v1);
            st_peer(ra + 832,  v2);
            st_peer(ra + 1248, v3);
            arrive_peer(mb_r + (HB ^ 1) * 8);   // release.cluster
        }
        __syncthreads();
    };

    unsigned pw0 = 0, pw1 = 0;
    ldW(Wa, 0); ldB(bA, 0);
    ldW(Wb, 1); ldB(bB, 1);

    #pragma unroll 1
    for (int l = 0; l < N_LAYERS; l += 2) {
        // layer l (even): reads h[0]
        if (l) {
            if (waiter) waitp(mb0, pw0);
            pw0 ^= 1;
        }
        do_layer(Wa, bA, 0);
        ldW(Wa, (size_t)l + 2); ldB(bA, l + 2);

        // layer l+1 (odd): reads h[1] (written by layer l)
        if (waiter) waitp(mb0 + 8, pw1);
        pw1 ^= 1;
        do_layer(Wb, bB, 1);
        ldW(Wb, (size_t)l + 3); ldB(bB, l + 3);
    }

    // Final Linear(100, 10): rank 0 writes; needs full h[0] (peer half
    // arrives via mbar[0] from layer 9999).
    if (rank == 0 && tid < 4 * D_OUT) {
        waitp(mb0, pw0);
        int r = tid / D_OUT, o = tid % D_OUT;
        const float* hr = h[0][r];
        float acc = bo[o];
        #pragma unroll
        for (int k = 0; k < D; k++)
            acc += hr[k] * __ldg(&Wo[(size_t)o * D + k]);
        out[(size_t)(r0 + r) * D_OUT + o] = acc;
    }

    // No CTA may exit while peer DSMEM stores could be in flight.
    asm volatile("barrier.cluster.arrive.aligned;" ::: "memory");
    asm volatile("barrier.cluster.wait.aligned;"   ::: "memory");
}

// ---------------------------------------------------------------------------
extern "C" void kernel_launch(void* const* d_in, const int* in_sizes, int n_in,
                              void* d_out, int out_size) {
    const float *x = nullptr, *W = nullptr, *b = nullptr, *Wo = nullptr, *bo = nullptr;
    for (int i = 0; i < n_in; i++) {
        switch (in_sizes[i]) {
            case 25600:     x  = (const float*)d_in[i]; break;
            case 100000000: W  = (const float*)d_in[i]; break;
            case 1000000:   b  = (const float*)d_in[i]; break;
            case 1000:      Wo = (const float*)d_in[i]; break;
            case 10:        bo = (const float*)d_in[i]; break;
            default: break;
        }
    }

    const size_t total = (size_t)(N_LAYERS + 2) * 2 * CSTRIDE;
    prep_kernel<<<(int)((total + 255) / 256), 256>>>(W);

    hugenet_kernel<<<128, THREADS>>>(x, b, Wo, bo, (float*)d_out);
}

// round 16
// speedup vs baseline: 1.4298x; 1.4298x over previous
#include <cuda_runtime.h>
#include <cstdint>
#include <cstddef>

// HugeNet: 10000 x (Linear(100,100)+ReLU) scan, then Linear(100,10).
//
// Round 16: L1tex-queue fix. R5 skeleton (64 CTAs x 4 rows, 256 threads,
// intra-warp 4-way k-split kq=tid&3, shfl_xor reduce, ONE barrier/layer)
// with the W prefetch MOVED to after the h-LDS/FMA block: ldW reloads the
// just-consumed register buffer (WAR dependence pins the LDGs after the
// critical LDS burst; consumption is 2 layers away so LDG latency stays
// hidden). Plus m<50 predication on ldW (no pad fetch).

#define N_LAYERS 10000
#define D        100
#define D_OUT    10
#define NCTA     64
#define THREADS  256
#define HSTR     104
#define WSLOTS   14               // max float4 per thread per layer (kq0: 2*7)

typedef unsigned long long ull;

// [(N_LAYERS+2)][WSLOTS][256] float4 (~573MB, zero-padded)
__device__ __align__(16) float4 g_Wp[(size_t)(N_LAYERS + 2) * WSLOTS * THREADS];

__host__ __device__ __forceinline__ int kq_base(int kq) {
    return (kq == 0) ? 0 : (28 + 24 * (kq - 1));   // {0,28,52,76}
}
__host__ __device__ __forceinline__ int kq_nq(int kq) {
    return (kq == 0) ? 7 : 6;                      // widths {28,24,24,24}
}
__host__ __device__ __forceinline__ void tmap(int t, int& m, int& kq) {
    kq = t & 3;
    m  = (t >> 5) * 8 + ((t >> 2) & 7);
}

// ---------------------------------------------------------------------------
// prep: W[l][j][k] row-major -> g_Wp[(l*WSLOTS + i)*256 + t]
//   i = 2q+jj; j = 2m+jj; k = kq_base(kq)+4q
// ---------------------------------------------------------------------------
__global__ void prep_kernel(const float* __restrict__ W) {
    size_t idx = (size_t)blockIdx.x * blockDim.x + threadIdx.x;
    const size_t total = (size_t)(N_LAYERS + 2) * WSLOTS * THREADS;
    if (idx >= total) return;
    int    t    = (int)(idx & (THREADS - 1));
    size_t rest = idx >> 8;
    int    i    = (int)(rest % WSLOTS);
    size_t l    = rest / WSLOTS;
    int m, kq;  tmap(t, m, kq);
    int jj = i & 1, q = i >> 1;
    int j  = 2 * m + jj;
    int k  = kq_base(kq) + 4 * q;
    float4 v = make_float4(0.f, 0.f, 0.f, 0.f);
    if (l < N_LAYERS && j < D && q < kq_nq(kq))
        v = *reinterpret_cast<const float4*>(
                W + l * (size_t)(D * D) + (size_t)j * D + k);
    g_Wp[idx] = v;
}

// ---------------------------------------------------------------------------
__device__ __forceinline__ void fma2(ull& a, ull x, ull y) {
    asm("fma.rn.f32x2 %0, %1, %2, %0;" : "+l"(a) : "l"(x), "l"(y));
}
__device__ __forceinline__ float2 upk(ull v) {
    float2 r;
    asm("mov.b64 {%0, %1}, %2;" : "=f"(r.x), "=f"(r.y) : "l"(v));
    return r;
}

__global__ void __launch_bounds__(THREADS, 1)
hugenet_kernel(const float* __restrict__ x,
               const float* __restrict__ bg,
               const float* __restrict__ Wo,
               const float* __restrict__ bo,
               float* __restrict__ out) {
    __shared__ float h[2][4][HSTR];

    const int tid = threadIdx.x;
    int m, kq;  tmap(tid, m, kq);
    const int nq = kq_nq(kq);
    const int kb = kq_base(kq);
    const int r0 = blockIdx.x * 4;
    const bool live   = (m < 50);
    const bool writer = live && (kq == 0);
    const unsigned red_mask = __ballot_sync(0xffffffffu, live);

    for (int idx = tid; idx < 4 * D; idx += THREADS) {
        int r = idx / D, k = idx % D;
        h[0][r][k] = x[(size_t)(r0 + r) * D + k];
    }
    __syncthreads();

    float4 Wa[WSLOTS], Wb[WSLOTS];
    float2 bA = make_float2(0.f, 0.f), bB = bA;

    auto ldW = [&](float4* R, size_t l) {
        if (!live) return;
        const float4* p = g_Wp + l * (WSLOTS * THREADS) + tid;
        #pragma unroll
        for (int i = 0; i < WSLOTS; i++)
            if (i < 2 * nq) R[i] = __ldg(p + (size_t)i * THREADS);
    };
    auto ldB = [&](float2& bb, int l) {
        if (writer && l < N_LAYERS)
            bb = *reinterpret_cast<const float2*>(bg + (size_t)l * D + 2 * m);
    };

    // One layer: read h[HB], write h[HB^1]. After the FMA block (all h-LDS
    // and all reads of R done), reload R with layer `nextl` — the WAR
    // dependence on R's registers keeps these LDGs AFTER the critical LDS
    // burst, so this layer's (and the next layer's) LDS don't queue behind
    // them in the L1tex FIFO.
    auto do_layer = [&](float4* R, float2& bias, int HB, size_t nextl) {
        ull a[8] = {0ull,0ull,0ull,0ull,0ull,0ull,0ull,0ull};
        if (live) {
            #pragma unroll
            for (int q = 0; q < 7; q++) {
                if (q < nq) {
                    ulonglong2 w0 = *reinterpret_cast<const ulonglong2*>(&R[2*q]);
                    ulonglong2 w1 = *reinterpret_cast<const ulonglong2*>(&R[2*q+1]);
                    #pragma unroll
                    for (int r = 0; r < 4; r++) {
                        ulonglong2 hv = *reinterpret_cast<const ulonglong2*>(
                                            &h[HB][r][kb + 4 * q]);
                        fma2(a[r],     hv.x, w0.x);
                        fma2(a[r],     hv.y, w0.y);
                        fma2(a[4 + r], hv.x, w1.x);
                        fma2(a[4 + r], hv.y, w1.y);
                    }
                }
            }
        }

        ldW(R, nextl);                    // prefetch into just-freed buffer

        if (live) {
            float s[8];
            #pragma unroll
            for (int i = 0; i < 8; i++) {
                float2 u = upk(a[i]);
                s[i] = u.x + u.y;
            }
            #pragma unroll
            for (int i = 0; i < 8; i++)
                s[i] += __shfl_xor_sync(red_mask, s[i], 1);
            #pragma unroll
            for (int i = 0; i < 8; i++)
                s[i] += __shfl_xor_sync(red_mask, s[i], 2);

            if (kq == 0) {
                #pragma unroll
                for (int r = 0; r < 4; r++) {
                    float v0 = fmaxf(s[r]     + bias.x, 0.f);
                    float v1 = fmaxf(s[4 + r] + bias.y, 0.f);
                    *reinterpret_cast<float2*>(&h[HB ^ 1][r][2 * m]) =
                        make_float2(v0, v1);
                }
            }
        }
        ldB(bias, (int)nextl);            // reload bias after use
        __syncthreads();
    };

    ldW(Wa, 0);  ldB(bA, 0);
    ldW(Wb, 1);  ldB(bB, 1);

    #pragma unroll 1
    for (int l = 0; l < N_LAYERS; l += 2) {
        do_layer(Wa, bA, 0, (size_t)l + 2);   // h[0] -> h[1]; Wa <- l+2
        do_layer(Wb, bB, 1, (size_t)l + 3);   // h[1] -> h[0]; Wb <- l+3
    }

    // Final Linear(100, 10): 40 threads, one (row, out-col). h in h[0].
    if (tid < 4 * D_OUT) {
        int r = tid / D_OUT, o = tid % D_OUT;
        const float* hr = h[0][r];
        float acc = bo[o];
        #pragma unroll
        for (int k = 0; k < D; k++)
            acc += hr[k] * __ldg(&Wo[(size_t)o * D + k]);
        out[(size_t)(r0 + r) * D_OUT + o] = acc;
    }
}

// ---------------------------------------------------------------------------
extern "C" void kernel_launch(void* const* d_in, const int* in_sizes, int n_in,
                              void* d_out, int out_size) {
    const float *x = nullptr, *W = nullptr, *b = nullptr, *Wo = nullptr, *bo = nullptr;
    for (int i = 0; i < n_in; i++) {
        switch (in_sizes[i]) {
            case 25600:     x  = (const float*)d_in[i]; break;
            case 100000000: W  = (const float*)d_in[i]; break;
            case 1000000:   b  = (const float*)d_in[i]; break;
            case 1000:      Wo = (const float*)d_in[i]; break;
            case 10:        bo = (const float*)d_in[i]; break;
            default: break;
        }
    }

    const size_t total = (size_t)(N_LAYERS + 2) * WSLOTS * THREADS;
    prep_kernel<<<(int)((total + 255) / 256), 256>>>(W);

    hugenet_kernel<<<NCTA, THREADS>>>(x, b, Wo, bo, (float*)d_out);
}

// round 17
// speedup vs baseline: 1.8327x; 1.2818x over previous
#include <cuda_runtime.h>
#include <cstdint>
#include <cstddef>

// HugeNet: 10000 x (Linear(100,100)+ReLU) scan, then Linear(100,10).
//
// Round 17: R3 (best, 8972us) + exactly two micro-fixes, nothing else:
//  (a) ldW predicated on m<50 -> fetch exactly 40KB W/layer (was 57KB)
//  (b) phase-2 parallel over 200 threads (one (row, col-pair) each)
//      instead of 50 threads doing 4 rows each -> shorter serial tail.
// Skeleton unchanged: 64 CTAs x 4 rows, 256 threads,
// kq = tid>>6 (k-groups {0:28,28:52,52:76,76:100}), m = tid&63 (col pair),
// W thread-interleaved fp32, double-buffered in registers, 2 barriers/layer.

#define N_LAYERS 10000
#define D        100
#define D_OUT    10
#define NCTA     64
#define THREADS  256
#define HSTR     104
#define WSLOTS   14               // max float4 per thread per layer (kq0: 2*7)

typedef unsigned long long ull;

// [(N_LAYERS+2)][WSLOTS][256] float4 (~573MB, zero-padded)
__device__ __align__(16) float4 g_Wp[(size_t)(N_LAYERS + 2) * WSLOTS * THREADS];

__host__ __device__ __forceinline__ int kq_base(int kq) {
    return (kq == 0) ? 0 : (28 + 24 * (kq - 1));   // {0,28,52,76}
}
__host__ __device__ __forceinline__ int kq_nq(int kq) {
    return (kq == 0) ? 7 : 6;                      // widths {28,24,24,24}
}

// ---------------------------------------------------------------------------
// prep: W[l][j][k] row-major -> g_Wp[(l*WSLOTS + i)*256 + t]   (same as R3)
//   t -> (m = t&63, kq = t>>6); i = 2q+jj; j = 2m+jj; k = kq_base+4q
// ---------------------------------------------------------------------------
__global__ void prep_kernel(const float* __restrict__ W) {
    size_t idx = (size_t)blockIdx.x * blockDim.x + threadIdx.x;
    const size_t total = (size_t)(N_LAYERS + 2) * WSLOTS * THREADS;
    if (idx >= total) return;
    int    t    = (int)(idx & (THREADS - 1));
    size_t rest = idx >> 8;
    int    i    = (int)(rest % WSLOTS);
    size_t l    = rest / WSLOTS;
    int m  = t & 63, kq = t >> 6;
    int jj = i & 1,  q  = i >> 1;
    int j  = 2 * m + jj;
    int k  = kq_base(kq) + 4 * q;
    float4 v = make_float4(0.f, 0.f, 0.f, 0.f);
    if (l < N_LAYERS && j < D && q < kq_nq(kq))
        v = *reinterpret_cast<const float4*>(
                W + l * (size_t)(D * D) + (size_t)j * D + k);
    g_Wp[idx] = v;
}

// ---------------------------------------------------------------------------
__device__ __forceinline__ void fma2(ull& a, ull x, ull y) {
    asm("fma.rn.f32x2 %0, %1, %2, %0;" : "+l"(a) : "l"(x), "l"(y));
}
__device__ __forceinline__ float2 upk(ull v) {
    float2 r;
    asm("mov.b64 {%0, %1}, %2;" : "=f"(r.x), "=f"(r.y) : "l"(v));
    return r;
}

__global__ void __launch_bounds__(THREADS, 1)
hugenet_kernel(const float* __restrict__ x,
               const float* __restrict__ bg,
               const float* __restrict__ Wo,
               const float* __restrict__ bo,
               float* __restrict__ out) {
    __shared__ float h[2][4][HSTR];
    __shared__ float red[4][8][64];   // [kq][jj*4+r][m]  (all 4 groups now)

    const int tid = threadIdx.x;
    const int m   = tid & 63;
    const int kq  = tid >> 6;
    const int nq  = kq_nq(kq);
    const int kb  = kq_base(kq);
    const int r0  = blockIdx.x * 4;
    const bool live = (m < 50);                // fix (a): gate W fetch

    // fix (b): phase-2 role, 200 threads, one (row r2, col-pair jp) each
    const bool p2 = (tid < 200);
    const int  r2 = tid / 50;
    const int  jp = tid - 50 * r2;

    for (int idx = tid; idx < 4 * D; idx += THREADS) {
        int r = idx / D, k = idx % D;
        h[0][r][k] = x[(size_t)(r0 + r) * D + k];
    }
    __syncthreads();

    float4 Wa[WSLOTS] = {}, Wb[WSLOTS] = {};
    float2 bA = make_float2(0.f, 0.f), bB = bA;

    auto ldW = [&](float4* R, size_t l) {
        if (!live) return;                     // fix (a)
        const float4* p = g_Wp + l * (WSLOTS * THREADS) + tid;
        #pragma unroll
        for (int i = 0; i < WSLOTS; i++)
            if (i < 2 * nq) R[i] = __ldg(p + (size_t)i * THREADS);
    };
    auto ldB = [&](float2& bb, int l) {
        if (p2 && l < N_LAYERS)
            bb = *reinterpret_cast<const float2*>(bg + (size_t)l * D + 2 * jp);
    };

    auto do_layer = [&](const float4* R, float2 bias, int HB) {
        // ---- phase 1 (as R3): partial dots, this thread's k-group ----
        ull a[8] = {0ull,0ull,0ull,0ull,0ull,0ull,0ull,0ull};
        #pragma unroll
        for (int q = 0; q < 7; q++) {
            if (q < nq) {
                ulonglong2 w0 = *reinterpret_cast<const ulonglong2*>(&R[2*q]);
                ulonglong2 w1 = *reinterpret_cast<const ulonglong2*>(&R[2*q+1]);
                #pragma unroll
                for (int r = 0; r < 4; r++) {
                    ulonglong2 hv = *reinterpret_cast<const ulonglong2*>(
                                        &h[HB][r][kb + 4 * q]);
                    fma2(a[r],     hv.x, w0.x);
                    fma2(a[r],     hv.y, w0.y);
                    fma2(a[4 + r], hv.x, w1.x);
                    fma2(a[4 + r], hv.y, w1.y);
                }
            }
        }
        #pragma unroll
        for (int i = 0; i < 8; i++) {
            float2 u = upk(a[i]);
            red[kq][i][m] = u.x + u.y;
        }
        __syncthreads();

        // ---- phase 2 (fix b): 200 threads, one (row, col-pair) each ----
        if (p2) {
            float s0 = ((red[0][r2][jp]     + red[1][r2][jp])
                      + (red[2][r2][jp]     + red[3][r2][jp])) + bias.x;
            float s1 = ((red[0][4 + r2][jp] + red[1][4 + r2][jp])
                      + (red[2][4 + r2][jp] + red[3][4 + r2][jp])) + bias.y;
            *reinterpret_cast<float2*>(&h[HB ^ 1][r2][2 * jp]) =
                make_float2(fmaxf(s0, 0.f), fmaxf(s1, 0.f));
        }
        __syncthreads();
    };

    ldW(Wa, 0);
    ldB(bA, 0);

    #pragma unroll 1
    for (int l = 0; l < N_LAYERS; l += 2) {
        ldW(Wb, (size_t)l + 1);
        ldB(bB, l + 1);

        do_layer(Wa, bA, 0);              // h[0] -> h[1]

        ldW(Wa, (size_t)l + 2);           // pad layers zeroed
        ldB(bA, l + 2);

        do_layer(Wb, bB, 1);              // h[1] -> h[0]
    }

    // Final Linear(100, 10): 40 threads, one (row, out-col). h in h[0].
    if (tid < 4 * D_OUT) {
        int r = tid / D_OUT, o = tid % D_OUT;
        const float* hr = h[0][r];
        float acc = bo[o];
        #pragma unroll
        for (int k = 0; k < D; k++)
            acc += hr[k] * __ldg(&Wo[(size_t)o * D + k]);
        out[(size_t)(r0 + r) * D_OUT + o] = acc;
    }
}

// ---------------------------------------------------------------------------
extern "C" void kernel_launch(void* const* d_in, const int* in_sizes, int n_in,
                              void* d_out, int out_size) {
    const float *x = nullptr, *W = nullptr, *b = nullptr, *Wo = nullptr, *bo = nullptr;
    for (int i = 0; i < n_in; i++) {
        switch (in_sizes[i]) {
            case 25600:     x  = (const float*)d_in[i]; break;
            case 100000000: W  = (const float*)d_in[i]; break;
            case 1000000:   b  = (const float*)d_in[i]; break;
            case 1000:      Wo = (const float*)d_in[i]; break;
            case 10:        bo = (const float*)d_in[i]; break;
            default: break;
        }
    }

    const size_t total = (size_t)(N_LAYERS + 2) * WSLOTS * THREADS;
    prep_kernel<<<(int)((total + 255) / 256), 256>>>(W);

    hugenet_kernel<<<NCTA, THREADS>>>(x, b, Wo, bo, (float*)d_out);
}